// round 4
// baseline (speedup 1.0000x reference)
#include <cuda_runtime.h>

// ---------------- problem constants ----------------
#define NN     50000
#define EE     800000
#define HIDN   96
#define GK     128      // padded K for both GEMMs (gemm2 K=106 zero-padded)
#define NODEF  128
#define TEMPF  10

// ---------------- device scratch (no allocations allowed) ----------------
__device__ __align__(16) float g_dinv [NN];           // rsqrt(deg+1)
__device__ __align__(16) float g_hs   [NN * HIDN];    // dinv[i] * (x @ W_gcn)
__device__ __align__(16) float g_acat [NN * GK];      // [relu(dinv*agg+b_gcn) | temporal | 0]
__device__ __align__(16) float g_w1p  [GK * HIDN];    // W1 zero-padded 106->128 rows
__device__ __align__(16) float g_h2   [NN * HIDN];    // layer-2 activations
__device__ int   g_cnt [NN];                          // in-degree (excl. self loop)
__device__ int   g_row [NN];                          // CSR row start
__device__ int   g_woff[NN];                          // CSR fill cursor
__device__ int   g_csr [EE];                          // src ids grouped by dst

// ---------------- CSR build ----------------
__global__ void k_zero_cnt(int n) {
    int i = blockIdx.x * blockDim.x + threadIdx.x;
    if (i < n) g_cnt[i] = 0;
}

// NOTE: edge_index is int32 (JAX default config demotes int64 -> int32).
__global__ void k_count(const int* __restrict__ ei, int E) {
    int e = blockIdx.x * blockDim.x + threadIdx.x;
    if (e < E) atomicAdd(&g_cnt[ei[E + e]], 1);
}

// single-block exclusive scan over n counts; also computes dinv
__global__ void __launch_bounds__(1024) k_scan(int n) {
    __shared__ int ws[32];
    __shared__ int s_carry;
    int tid = threadIdx.x, lane = tid & 31, w = tid >> 5;
    if (tid == 0) s_carry = 0;
    __syncthreads();
    for (int base = 0; base < n; base += 1024) {
        int i = base + tid;
        int v = (i < n) ? g_cnt[i] : 0;
        int x = v;
#pragma unroll
        for (int o = 1; o < 32; o <<= 1) {
            int y = __shfl_up_sync(0xffffffffu, x, o);
            if (lane >= o) x += y;
        }
        if (lane == 31) ws[w] = x;
        __syncthreads();
        if (w == 0) {
            int y = ws[lane];
#pragma unroll
            for (int o = 1; o < 32; o <<= 1) {
                int z = __shfl_up_sync(0xffffffffu, y, o);
                if (lane >= o) y += z;
            }
            ws[lane] = y;
        }
        __syncthreads();
        int incl = x + (w > 0 ? ws[w - 1] : 0) + s_carry;
        if (i < n) {
            int excl = incl - v;
            g_row [i] = excl;
            g_woff[i] = excl;
            g_dinv[i] = rsqrtf((float)(v + 1));   // +1 self loop
        }
        __syncthreads();
        if (tid == 1023) s_carry = incl;
        __syncthreads();
    }
}

__global__ void k_fill(const int* __restrict__ ei, int E) {
    int e = blockIdx.x * blockDim.x + threadIdx.x;
    if (e >= E) return;
    int src = ei[e];
    int dst = ei[E + e];
    int pos = atomicAdd(&g_woff[dst], 1);
    g_csr[pos] = src;
}

// ---------------- GEMM: C[M,96] = A[M,128] @ B[128,96] (+ epilogue) ----------------
// mode 0: A=x, B=W_gcn; v = acc * g_dinv[m]  -> g_hs
// mode 1: A=g_acat, B=g_w1p; v = relu(acc + bias[j]) -> g_h2
__global__ void __launch_bounds__(256) k_gemm(
    const float* __restrict__ A_ext,
    const float* __restrict__ B_ext,
    const float* __restrict__ bias,
    int mode, int M)
{
    __shared__ float As[64][36];
    __shared__ float Bs[32][96];

    const float* __restrict__ A = (mode == 0) ? A_ext : g_acat;
    const float* __restrict__ B = (mode == 0) ? B_ext : g_w1p;

    int tid = threadIdx.x;
    int tx = tid & 15;        // 16 col groups x 6 cols = 96
    int ty = tid >> 4;        // 16 row groups x 4 rows = 64
    int row0 = blockIdx.x * 64;

    float acc[4][6];
#pragma unroll
    for (int r = 0; r < 4; r++)
#pragma unroll
        for (int c = 0; c < 6; c++) acc[r][c] = 0.0f;

    for (int kc = 0; kc < 4; kc++) {
        int k0 = kc * 32;
#pragma unroll
        for (int i = tid; i < 64 * 8; i += 256) {
            int m = i >> 3, kq = i & 7;
            int gm = row0 + m;
            float4 v = make_float4(0.f, 0.f, 0.f, 0.f);
            if (gm < M)
                v = reinterpret_cast<const float4*>(A + (size_t)gm * GK + k0)[kq];
            *reinterpret_cast<float4*>(&As[m][kq * 4]) = v;
        }
#pragma unroll
        for (int i = tid; i < 32 * 24; i += 256) {
            int kk = i / 24, jq = i % 24;
            *reinterpret_cast<float4*>(&Bs[kk][jq * 4]) =
                reinterpret_cast<const float4*>(B + (size_t)(k0 + kk) * HIDN)[jq];
        }
        __syncthreads();

#pragma unroll
        for (int kk = 0; kk < 32; kk += 4) {
            float4 a[4];
#pragma unroll
            for (int r = 0; r < 4; r++)
                a[r] = *reinterpret_cast<const float4*>(&As[ty * 4 + r][kk]);
            float bv[4][6];
#pragma unroll
            for (int q = 0; q < 4; q++) {
                float2 t0 = *reinterpret_cast<const float2*>(&Bs[kk + q][tx * 6]);
                float2 t1 = *reinterpret_cast<const float2*>(&Bs[kk + q][tx * 6 + 2]);
                float2 t2 = *reinterpret_cast<const float2*>(&Bs[kk + q][tx * 6 + 4]);
                bv[q][0] = t0.x; bv[q][1] = t0.y;
                bv[q][2] = t1.x; bv[q][3] = t1.y;
                bv[q][4] = t2.x; bv[q][5] = t2.y;
            }
#pragma unroll
            for (int r = 0; r < 4; r++) {
                float av[4] = { a[r].x, a[r].y, a[r].z, a[r].w };
#pragma unroll
                for (int q = 0; q < 4; q++)
#pragma unroll
                    for (int c = 0; c < 6; c++)
                        acc[r][c] = fmaf(av[q], bv[q][c], acc[r][c]);
            }
        }
        __syncthreads();
    }

#pragma unroll
    for (int r = 0; r < 4; r++) {
        int m = row0 + ty * 4 + r;
        if (m < M) {
            if (mode == 0) {
                float s = g_dinv[m];
#pragma unroll
                for (int c = 0; c < 6; c++)
                    g_hs[(size_t)m * HIDN + tx * 6 + c] = acc[r][c] * s;
            } else {
#pragma unroll
                for (int c = 0; c < 6; c++) {
                    int j = tx * 6 + c;
                    g_h2[(size_t)m * HIDN + j] = fmaxf(acc[r][c] + bias[j], 0.0f);
                }
            }
        }
    }
}

// ---------------- gather segment-sum + fused acat pack ----------------
// one warp per dst node: acc = hs[i] + sum_{src in CSR row} hs[src]
// acat[i] = [ relu(dinv[i]*acc + b_gcn) | temporal[i] | 0-pad ]
__global__ void __launch_bounds__(256) k_gather(
    const float* __restrict__ temporal,
    const float* __restrict__ b_gcn, int n)
{
    int gw   = (blockIdx.x * blockDim.x + threadIdx.x) >> 5;
    int lane = threadIdx.x & 31;
    if (gw >= n) return;
    int i = gw;

    float4 acc = make_float4(0.f, 0.f, 0.f, 0.f);
    if (lane < 24)
        acc = reinterpret_cast<const float4*>(g_hs)[(size_t)i * 24 + lane];  // self loop

    int start = g_row[i];
    int cnt   = g_cnt[i];
    for (int base = 0; base < cnt; base += 32) {
        int e = base + lane;
        int s = (e < cnt) ? g_csr[start + e] : 0;
        int m = min(32, cnt - base);
        for (int j = 0; j < m; j++) {
            int src = __shfl_sync(0xffffffffu, s, j);
            if (lane < 24) {
                float4 v = reinterpret_cast<const float4*>(g_hs)[(size_t)src * 24 + lane];
                acc.x += v.x; acc.y += v.y; acc.z += v.z; acc.w += v.w;
            }
        }
    }

    float di = g_dinv[i];
    if (lane < 24) {
        float4 b = reinterpret_cast<const float4*>(b_gcn)[lane];
        float4 o;
        o.x = fmaxf(fmaf(di, acc.x, b.x), 0.0f);
        o.y = fmaxf(fmaf(di, acc.y, b.y), 0.0f);
        o.z = fmaxf(fmaf(di, acc.z, b.z), 0.0f);
        o.w = fmaxf(fmaf(di, acc.w, b.w), 0.0f);
        reinterpret_cast<float4*>(g_acat)[(size_t)i * 32 + lane] = o;
    } else {
        // cols 96..127: 10 temporal + 22 zero-pad, 4 cols per lane
#pragma unroll
        for (int q = 0; q < 4; q++) {
            int c = 96 + (lane - 24) * 4 + q;
            float v = (c < HIDN + TEMPF) ? temporal[(size_t)i * TEMPF + (c - HIDN)] : 0.0f;
            g_acat[(size_t)i * GK + c] = v;
        }
    }
}

// ---------------- pack W1 (zero-pad 106 -> 128 rows) ----------------
__global__ void k_pack_w1(const float* __restrict__ W1) {
    int idx = blockIdx.x * blockDim.x + threadIdx.x;
    if (idx >= GK * HIDN) return;
    int k = idx / HIDN, j = idx % HIDN;
    g_w1p[idx] = (k < HIDN + TEMPF) ? W1[(size_t)k * HIDN + j] : 0.0f;
}

// ---------------- final: out[i] = relu(h2[i]·W2[0:96] + x[i]·W2[96:224] + b2) ----------------
__global__ void k_final(const float* __restrict__ x,
                        const float* __restrict__ W2,
                        const float* __restrict__ b2,
                        float* __restrict__ out, int n) {
    int t = blockIdx.x * blockDim.x + threadIdx.x;
    int i = t >> 5, lane = t & 31;
    if (i >= n) return;
    float acc = 0.0f;
    if (lane < 24) {
        float4 a = reinterpret_cast<const float4*>(g_h2)[(size_t)i * 24 + lane];
        float4 w = reinterpret_cast<const float4*>(W2)[lane];
        acc = a.x * w.x + a.y * w.y + a.z * w.z + a.w * w.w;
    }
    {
        float4 a = reinterpret_cast<const float4*>(x)[(size_t)i * 32 + lane];
        float4 w = reinterpret_cast<const float4*>(W2 + HIDN)[lane];
        acc += a.x * w.x + a.y * w.y + a.z * w.z + a.w * w.w;
    }
#pragma unroll
    for (int o = 16; o; o >>= 1) acc += __shfl_down_sync(0xffffffffu, acc, o);
    if (lane == 0) out[i] = fmaxf(acc + b2[0], 0.0f);
}

// ---------------- launch ----------------
extern "C" void kernel_launch(void* const* d_in, const int* in_sizes, int n_in,
                              void* d_out, int out_size) {
    const float* x        = (const float*)d_in[0];
    const int*   ei       = (const int*)  d_in[1];   // int32! (JAX x64 disabled)
    const float* temporal = (const float*)d_in[2];
    const float* W_gcn    = (const float*)d_in[3];
    const float* b_gcn    = (const float*)d_in[4];
    const float* W1       = (const float*)d_in[5];
    const float* b1       = (const float*)d_in[6];
    const float* W2       = (const float*)d_in[7];
    const float* b2       = (const float*)d_in[8];
    float*       out      = (float*)d_out;

    int N = in_sizes[0] / NODEF;   // 50000
    int E = in_sizes[1] / 2;       // 800000

    k_zero_cnt <<<(N + 255) / 256, 256>>>(N);
    k_count    <<<(E + 255) / 256, 256>>>(ei, E);
    k_scan     <<<1, 1024>>>(N);
    k_fill     <<<(E + 255) / 256, 256>>>(ei, E);

    k_gemm     <<<(N + 63) / 64, 256>>>(x, W_gcn, nullptr, 0, N);   // g_hs
    k_pack_w1  <<<(GK * HIDN + 255) / 256, 256>>>(W1);

    k_gather   <<<(N * 32 + 255) / 256, 256>>>(temporal, b_gcn, N); // g_acat

    k_gemm     <<<(N + 63) / 64, 256>>>(nullptr, nullptr, b1, 1, N); // g_h2
    k_final    <<<(N * 32 + 255) / 256, 256>>>(x, W2, b2, out, N);
}

// round 5
// speedup vs baseline: 1.3650x; 1.3650x over previous
#include <cuda_runtime.h>

// ---------------- problem constants ----------------
#define NN     50000
#define EE     800000
#define HIDN   96
#define GK     128      // padded K for both GEMMs (gemm2 K=106 zero-padded)
#define NODEF  128
#define TEMPF  10
#define NB256  ((NN + 255) / 256)   // 196 blocks for scan

// ---------------- device scratch (no allocations allowed) ----------------
__device__ __align__(16) float g_dinv [NN];           // rsqrt(deg+1)
__device__ __align__(16) float g_hs   [NN * HIDN];    // dinv[i] * (x @ W_gcn)
__device__ __align__(16) float g_acat [NN * GK];      // [relu(dinv*agg+b_gcn) | temporal | 0]
__device__ __align__(16) float g_w1p  [GK * HIDN];    // W1 zero-padded 106->128 rows
__device__ __align__(16) float g_xw2  [NN];           // x[m] . W2[96:224]
__device__ int   g_cnt [NN];                          // in-degree (excl. self loop)
__device__ int   g_row [NN];                          // CSR row start
__device__ int   g_woff[NN];                          // CSR fill cursor
__device__ int   g_csr [EE];                          // src ids grouped by dst
__device__ int   g_bsum[256];                         // per-block count sums
__device__ int   g_boff[256];                         // exclusive block offsets

// ---------------- CSR build ----------------
__global__ void k_zero_cnt(int n) {
    int i = blockIdx.x * blockDim.x + threadIdx.x;
    if (i < n) g_cnt[i] = 0;
}

// edge_index is int32 (JAX default config demotes int64 -> int32)
__global__ void k_count(const int* __restrict__ ei, int E) {
    int e = blockIdx.x * blockDim.x + threadIdx.x;
    if (e < E) atomicAdd(&g_cnt[ei[E + e]], 1);
}

// stage 1: per-block exclusive scan of counts; block totals to g_bsum
__global__ void __launch_bounds__(256) k_scan_blk(int n) {
    __shared__ int ws[8];
    int tid = threadIdx.x, lane = tid & 31, w = tid >> 5;
    int i = blockIdx.x * 256 + tid;
    int v = (i < n) ? g_cnt[i] : 0;
    int x = v;
#pragma unroll
    for (int o = 1; o < 32; o <<= 1) {
        int y = __shfl_up_sync(0xffffffffu, x, o);
        if (lane >= o) x += y;
    }
    if (lane == 31) ws[w] = x;
    __syncthreads();
    if (tid < 8) {
        int y = ws[tid];
#pragma unroll
        for (int o = 1; o < 8; o <<= 1) {
            int z = __shfl_up_sync(0xffu, y, o);
            if ((int)tid >= o) y += z;
        }
        ws[tid] = y;
    }
    __syncthreads();
    int excl = x - v + (w ? ws[w - 1] : 0);
    if (i < n) g_row[i] = excl;                 // block-local for now
    if (tid == 0) g_bsum[blockIdx.x] = ws[7];   // block total
}

// stage 2: single-block scan of <=256 block totals
__global__ void __launch_bounds__(256) k_scan_top(int nb) {
    __shared__ int ws[8];
    int tid = threadIdx.x, lane = tid & 31, w = tid >> 5;
    int v = (tid < nb) ? g_bsum[tid] : 0;
    int x = v;
#pragma unroll
    for (int o = 1; o < 32; o <<= 1) {
        int y = __shfl_up_sync(0xffffffffu, x, o);
        if (lane >= o) x += y;
    }
    if (lane == 31) ws[w] = x;
    __syncthreads();
    if (tid < 8) {
        int y = ws[tid];
#pragma unroll
        for (int o = 1; o < 8; o <<= 1) {
            int z = __shfl_up_sync(0xffu, y, o);
            if ((int)tid >= o) y += z;
        }
        ws[tid] = y;
    }
    __syncthreads();
    int excl = x - v + (w ? ws[w - 1] : 0);
    if (tid < nb) g_boff[tid] = excl;
}

// stage 3: add block offsets; init cursors; compute dinv
__global__ void k_scan_add(int n) {
    int i = blockIdx.x * blockDim.x + threadIdx.x;
    if (i >= n) return;
    int excl = g_row[i] + g_boff[i >> 8];
    g_row [i] = excl;
    g_woff[i] = excl;
    g_dinv[i] = rsqrtf((float)(g_cnt[i] + 1));   // +1 self loop
}

__global__ void k_fill(const int* __restrict__ ei, int E) {
    int e = blockIdx.x * blockDim.x + threadIdx.x;
    if (e >= E) return;
    int src = ei[e];
    int dst = ei[E + e];
    int pos = atomicAdd(&g_woff[dst], 1);
    g_csr[pos] = src;
}

// ---------------- GEMM: C[M,96] = A[M,128] @ B[128,96] ----------------
// mode 0: A=x, B=W_gcn; writes g_hs = acc*dinv[m]; ALSO accumulates g_xw2[m] = x[m].W2[96:224]
// mode 1: A=g_acat, B=g_w1p; fused final: out[m] = relu( relu(acc+b1).W2[0:96] + g_xw2[m] + b2 )
__global__ void __launch_bounds__(256) k_gemm(
    const float* __restrict__ A_ext,
    const float* __restrict__ B_ext,
    const float* __restrict__ bias,
    const float* __restrict__ W2,
    const float* __restrict__ b2,
    float* __restrict__ outp,
    int mode, int M)
{
    __shared__ float As[64][36];
    __shared__ float Bs[32][96];

    const float* __restrict__ A = (mode == 0) ? A_ext : g_acat;
    const float* __restrict__ B = (mode == 0) ? B_ext : g_w1p;

    int tid = threadIdx.x;
    int tx = tid & 15;        // 16 col groups x 6 cols = 96
    int ty = tid >> 4;        // 16 row groups x 4 rows = 64
    int row0 = blockIdx.x * 64;

    float acc[4][6];
#pragma unroll
    for (int r = 0; r < 4; r++)
#pragma unroll
        for (int c = 0; c < 6; c++) acc[r][c] = 0.0f;

    float px[4] = {0.f, 0.f, 0.f, 0.f};   // mode0: partial xw2

    float w2a[6];
    if (mode == 1) {
#pragma unroll
        for (int c = 0; c < 6; c++) w2a[c] = W2[tx * 6 + c];
    }

    for (int kc = 0; kc < 4; kc++) {
        int k0 = kc * 32;
#pragma unroll
        for (int i = tid; i < 64 * 8; i += 256) {
            int m = i >> 3, kq = i & 7;
            int gm = row0 + m;
            float4 v = make_float4(0.f, 0.f, 0.f, 0.f);
            if (gm < M)
                v = reinterpret_cast<const float4*>(A + (size_t)gm * GK + k0)[kq];
            *reinterpret_cast<float4*>(&As[m][kq * 4]) = v;
        }
#pragma unroll
        for (int i = tid; i < 32 * 24; i += 256) {
            int kk = i / 24, jq = i % 24;
            *reinterpret_cast<float4*>(&Bs[kk][jq * 4]) =
                reinterpret_cast<const float4*>(B + (size_t)(k0 + kk) * HIDN)[jq];
        }
        __syncthreads();

        if (mode == 0) {
            // side product: xw2 partial (each tx covers 2 k's of this chunk)
            float wb0 = W2[HIDN + k0 + tx * 2];
            float wb1 = W2[HIDN + k0 + tx * 2 + 1];
#pragma unroll
            for (int r = 0; r < 4; r++) {
                float a0 = As[ty * 4 + r][tx * 2];
                float a1 = As[ty * 4 + r][tx * 2 + 1];
                px[r] = fmaf(a0, wb0, fmaf(a1, wb1, px[r]));
            }
        }

#pragma unroll
        for (int kk = 0; kk < 32; kk += 4) {
            float4 a[4];
#pragma unroll
            for (int r = 0; r < 4; r++)
                a[r] = *reinterpret_cast<const float4*>(&As[ty * 4 + r][kk]);
            float bv[4][6];
#pragma unroll
            for (int q = 0; q < 4; q++) {
                float2 t0 = *reinterpret_cast<const float2*>(&Bs[kk + q][tx * 6]);
                float2 t1 = *reinterpret_cast<const float2*>(&Bs[kk + q][tx * 6 + 2]);
                float2 t2 = *reinterpret_cast<const float2*>(&Bs[kk + q][tx * 6 + 4]);
                bv[q][0] = t0.x; bv[q][1] = t0.y;
                bv[q][2] = t1.x; bv[q][3] = t1.y;
                bv[q][4] = t2.x; bv[q][5] = t2.y;
            }
#pragma unroll
            for (int r = 0; r < 4; r++) {
                float av[4] = { a[r].x, a[r].y, a[r].z, a[r].w };
#pragma unroll
                for (int q = 0; q < 4; q++)
#pragma unroll
                    for (int c = 0; c < 6; c++)
                        acc[r][c] = fmaf(av[q], bv[q][c], acc[r][c]);
            }
        }
        __syncthreads();
    }

    if (mode == 0) {
#pragma unroll
        for (int r = 0; r < 4; r++) {
            int m = row0 + ty * 4 + r;
            if (m < M) {
                float s = g_dinv[m];
#pragma unroll
                for (int c = 0; c < 6; c++)
                    g_hs[(size_t)m * HIDN + tx * 6 + c] = acc[r][c] * s;
            }
            // reduce xw2 partial over the 16 tx lanes (stays within half-warp)
            float p = px[r];
            p += __shfl_xor_sync(0xffffffffu, p, 1);
            p += __shfl_xor_sync(0xffffffffu, p, 2);
            p += __shfl_xor_sync(0xffffffffu, p, 4);
            p += __shfl_xor_sync(0xffffffffu, p, 8);
            if (tx == 0 && m < M) g_xw2[m] = p;
        }
    } else {
        float b2v = b2[0];
#pragma unroll
        for (int r = 0; r < 4; r++) {
            int m = row0 + ty * 4 + r;
            float p = 0.0f;
#pragma unroll
            for (int c = 0; c < 6; c++) {
                float v = fmaxf(acc[r][c] + bias[tx * 6 + c], 0.0f);
                p = fmaf(v, w2a[c], p);
            }
            p += __shfl_xor_sync(0xffffffffu, p, 1);
            p += __shfl_xor_sync(0xffffffffu, p, 2);
            p += __shfl_xor_sync(0xffffffffu, p, 4);
            p += __shfl_xor_sync(0xffffffffu, p, 8);
            if (tx == 0 && m < M)
                outp[m] = fmaxf(p + g_xw2[m] + b2v, 0.0f);
        }
    }
}

// ---------------- gather segment-sum + fused acat pack ----------------
__global__ void __launch_bounds__(256) k_gather(
    const float* __restrict__ temporal,
    const float* __restrict__ b_gcn, int n)
{
    int gw   = (blockIdx.x * blockDim.x + threadIdx.x) >> 5;
    int lane = threadIdx.x & 31;
    if (gw >= n) return;
    int i = gw;

    float4 acc = make_float4(0.f, 0.f, 0.f, 0.f);
    if (lane < 24)
        acc = reinterpret_cast<const float4*>(g_hs)[(size_t)i * 24 + lane];  // self loop

    int start = g_row[i];
    int cnt   = g_cnt[i];
    for (int base = 0; base < cnt; base += 32) {
        int e = base + lane;
        int s = (e < cnt) ? g_csr[start + e] : 0;
        int m = min(32, cnt - base);
        int j = 0;
        for (; j + 2 <= m; j += 2) {   // unroll x2 for load MLP
            int s0 = __shfl_sync(0xffffffffu, s, j);
            int s1 = __shfl_sync(0xffffffffu, s, j + 1);
            if (lane < 24) {
                float4 v0 = reinterpret_cast<const float4*>(g_hs)[(size_t)s0 * 24 + lane];
                float4 v1 = reinterpret_cast<const float4*>(g_hs)[(size_t)s1 * 24 + lane];
                acc.x += v0.x + v1.x; acc.y += v0.y + v1.y;
                acc.z += v0.z + v1.z; acc.w += v0.w + v1.w;
            }
        }
        if (j < m) {
            int s0 = __shfl_sync(0xffffffffu, s, j);
            if (lane < 24) {
                float4 v0 = reinterpret_cast<const float4*>(g_hs)[(size_t)s0 * 24 + lane];
                acc.x += v0.x; acc.y += v0.y; acc.z += v0.z; acc.w += v0.w;
            }
        }
    }

    float di = g_dinv[i];
    if (lane < 24) {
        float4 b = reinterpret_cast<const float4*>(b_gcn)[lane];
        float4 o;
        o.x = fmaxf(fmaf(di, acc.x, b.x), 0.0f);
        o.y = fmaxf(fmaf(di, acc.y, b.y), 0.0f);
        o.z = fmaxf(fmaf(di, acc.z, b.z), 0.0f);
        o.w = fmaxf(fmaf(di, acc.w, b.w), 0.0f);
        reinterpret_cast<float4*>(g_acat)[(size_t)i * 32 + lane] = o;
    } else {
#pragma unroll
        for (int q = 0; q < 4; q++) {
            int c = 96 + (lane - 24) * 4 + q;
            float v = (c < HIDN + TEMPF) ? temporal[(size_t)i * TEMPF + (c - HIDN)] : 0.0f;
            g_acat[(size_t)i * GK + c] = v;
        }
    }
}

// ---------------- pack W1 (zero-pad 106 -> 128 rows) ----------------
__global__ void k_pack_w1(const float* __restrict__ W1) {
    int idx = blockIdx.x * blockDim.x + threadIdx.x;
    if (idx >= GK * HIDN) return;
    int k = idx / HIDN, j = idx % HIDN;
    g_w1p[idx] = (k < HIDN + TEMPF) ? W1[(size_t)k * HIDN + j] : 0.0f;
}

// ---------------- launch ----------------
extern "C" void kernel_launch(void* const* d_in, const int* in_sizes, int n_in,
                              void* d_out, int out_size) {
    const float* x        = (const float*)d_in[0];
    const int*   ei       = (const int*)  d_in[1];   // int32 (JAX x64 disabled)
    const float* temporal = (const float*)d_in[2];
    const float* W_gcn    = (const float*)d_in[3];
    const float* b_gcn    = (const float*)d_in[4];
    const float* W1       = (const float*)d_in[5];
    const float* b1       = (const float*)d_in[6];
    const float* W2       = (const float*)d_in[7];
    const float* b2       = (const float*)d_in[8];
    float*       out      = (float*)d_out;

    int N  = in_sizes[0] / NODEF;   // 50000
    int E  = in_sizes[1] / 2;       // 800000
    int nb = (N + 255) / 256;       // 196

    k_zero_cnt <<<nb, 256>>>(N);
    k_count    <<<(E + 255) / 256, 256>>>(ei, E);
    k_scan_blk <<<nb, 256>>>(N);
    k_scan_top <<<1, 256>>>(nb);
    k_scan_add <<<nb, 256>>>(N);
    k_fill     <<<(E + 255) / 256, 256>>>(ei, E);

    k_gemm     <<<(N + 63) / 64, 256>>>(x, W_gcn, nullptr, W2, b2, nullptr, 0, N); // g_hs + g_xw2
    k_pack_w1  <<<(GK * HIDN + 255) / 256, 256>>>(W1);

    k_gather   <<<(N * 32 + 255) / 256, 256>>>(temporal, b_gcn, N);                // g_acat

    k_gemm     <<<(N + 63) / 64, 256>>>(nullptr, nullptr, b1, W2, b2, out, 1, N);  // fused final -> out
}